// round 4
// baseline (speedup 1.0000x reference)
#include <cuda_runtime.h>
#include <cuda_bf16.h>
#include <stdint.h>
#include <stddef.h>

// ============================================================================
// WindowAttention on sm_103 (baseline ISA: mma.sync HMMA, cp.async, ldmatrix)
//   qkv = x @ [Wq|Wk|Wv] + b      (M=100352, K=1024, N=1536, Wv zero-padded)
//   attn = softmax(q k^T * 0.125 + mask[b%256]) ; att = attn @ v
//   out  = att @ Wp + bp          (M=100352, K=512,  N=1024)
// GEMMs: split-bf16 (hi/lo, 3 HMMA passes, lo*lo dropped) fp32 accumulate.
// ============================================================================

#define M_ROWS   100352
#define N_QKV    1536
#define K_QKV    1024
#define N_PROJ   1024
#define K_PROJ   512

// ---------------- scratch (device globals; no allocation allowed) -----------
__device__ __align__(16) float          g_qkv[(size_t)M_ROWS * N_QKV];
__device__ __align__(16) __nv_bfloat16  g_x_hi[(size_t)M_ROWS * K_QKV];
__device__ __align__(16) __nv_bfloat16  g_x_lo[(size_t)M_ROWS * K_QKV];
__device__ __align__(16) __nv_bfloat16  g_att_hi[(size_t)M_ROWS * K_PROJ];
__device__ __align__(16) __nv_bfloat16  g_att_lo[(size_t)M_ROWS * K_PROJ];
__device__ __align__(16) __nv_bfloat16  g_wqkv_hi[(size_t)N_QKV * K_QKV];
__device__ __align__(16) __nv_bfloat16  g_wqkv_lo[(size_t)N_QKV * K_QKV];
__device__ __align__(16) __nv_bfloat16  g_wp_hi[(size_t)N_PROJ * K_PROJ];
__device__ __align__(16) __nv_bfloat16  g_wp_lo[(size_t)N_PROJ * K_PROJ];
__device__ float g_bqkv[N_QKV];

// ---------------- helpers ----------------------------------------------------
__device__ __forceinline__ uint32_t smem_u32(const void* p) {
    uint32_t a;
    asm("{ .reg .u64 t; cvta.to.shared.u64 t, %1; cvt.u32.u64 %0, t; }"
        : "=r"(a) : "l"(p));
    return a;
}

__device__ __forceinline__ void split_bf16(float x, __nv_bfloat16& h, __nv_bfloat16& l) {
    h = __float2bfloat16_rn(x);
    l = __float2bfloat16_rn(x - __bfloat162float(h));
}

#define CP16(dst, src) \
    asm volatile("cp.async.cg.shared.global [%0], [%1], 16;" \
                 :: "r"(dst), "l"(src))
#define CP_COMMIT() asm volatile("cp.async.commit_group;" ::: "memory")
#define CP_WAIT0()  asm volatile("cp.async.wait_group 0;" ::: "memory")
#define CP_WAIT1()  asm volatile("cp.async.wait_group 1;" ::: "memory")

#define LDMX4(r0, r1, r2, r3, addr) \
    asm volatile("ldmatrix.sync.aligned.m8n8.x4.shared.b16 {%0,%1,%2,%3}, [%4];" \
                 : "=r"(r0), "=r"(r1), "=r"(r2), "=r"(r3) : "r"(addr))

#define MMA16816(d, a, b0, b1) \
    asm volatile("mma.sync.aligned.m16n8k16.row.col.f32.bf16.bf16.f32 " \
                 "{%0,%1,%2,%3}, {%4,%5,%6,%7}, {%8,%9}, {%0,%1,%2,%3};" \
                 : "+f"((d)[0]), "+f"((d)[1]), "+f"((d)[2]), "+f"((d)[3]) \
                 : "r"((a)[0]), "r"((a)[1]), "r"((a)[2]), "r"((a)[3]), \
                   "r"(b0), "r"(b1))

// ============================================================================
// prep: weights (transposed, fused, hi/lo) + bias
// ============================================================================
__global__ void prep_w_kernel(const float* __restrict__ Wq, const float* __restrict__ Wk,
                              const float* __restrict__ Wv, const float* __restrict__ bq,
                              const float* __restrict__ bk, const float* __restrict__ bv,
                              const float* __restrict__ Wp)
{
    const int T1 = N_QKV * K_QKV;
    const int T2 = N_PROJ * K_PROJ;
    const int TOT = T1 + T2 + N_QKV;
    int stride = gridDim.x * blockDim.x;
    for (int idx = blockIdx.x * blockDim.x + threadIdx.x; idx < TOT; idx += stride) {
        if (idx < T1) {
            int n = idx >> 10, k = idx & 1023;
            float w;
            if (n < 512)       w = Wq[k * 512 + n];
            else if (n < 1024) w = Wk[k * 512 + (n - 512)];
            else               w = (k < 512) ? Wv[k * 512 + (n - 1024)] : 0.f;
            __nv_bfloat16 h, l; split_bf16(w, h, l);
            g_wqkv_hi[idx] = h; g_wqkv_lo[idx] = l;
        } else if (idx < T1 + T2) {
            int i = idx - T1;
            int n = i >> 9, k = i & 511;
            float w = Wp[k * 1024 + n];
            __nv_bfloat16 h, l; split_bf16(w, h, l);
            g_wp_hi[i] = h; g_wp_lo[i] = l;
        } else {
            int n = idx - T1 - T2;
            g_bqkv[n] = (n < 512) ? bq[n] : (n < 1024) ? bk[n - 512] : bv[n - 1024];
        }
    }
}

// x[M][1024] f32 -> hi/lo bf16 (8 floats per task)
__global__ void prep_x_kernel(const float* __restrict__ x)
{
    const size_t TOT = (size_t)M_ROWS * K_QKV / 8;
    size_t stride = (size_t)gridDim.x * blockDim.x;
    for (size_t t = blockIdx.x * (size_t)blockDim.x + threadIdx.x; t < TOT; t += stride) {
        const float4* src = (const float4*)(x + t * 8);
        float4 f0 = src[0], f1 = src[1];
        float v[8] = {f0.x, f0.y, f0.z, f0.w, f1.x, f1.y, f1.z, f1.w};
        __nv_bfloat16 h[8], l[8];
        #pragma unroll
        for (int e = 0; e < 8; ++e) split_bf16(v[e], h[e], l[e]);
        *(uint4*)(g_x_hi + t * 8) = *(uint4*)h;
        *(uint4*)(g_x_lo + t * 8) = *(uint4*)l;
    }
}

// ============================================================================
// split-bf16 GEMM: C[M][ldc] = A @ B^T + bias
//   A: hi/lo bf16 [M][lda] (K-major rows); B: hi/lo bf16 [N][ldb] (K-major rows)
//   CTA tile 128x128, K-chunk 64, 8 warps (2x4 -> warp tile 64x32)
//   smem/stage: Ahi|Alo|Bhi|Blo, each 128 rows x 72 bf16 (144B padded)
// ============================================================================
#define ROWB   144                  // padded row bytes (72 bf16)
#define ARRB   18432                // 128*144
#define STAGEB 73728                // 4*ARRB
#define GEMM_SMEM (2 * STAGEB)      // 147456

__global__ void __launch_bounds__(256, 1) gemm_kernel(
    const __nv_bfloat16* __restrict__ Ahi, const __nv_bfloat16* __restrict__ Alo, int lda,
    const __nv_bfloat16* __restrict__ Bhi, const __nv_bfloat16* __restrict__ Blo, int ldb,
    const float* __restrict__ bias,
    float* __restrict__ C, int ldc,
    int n_tiles, int k_chunks)
{
    extern __shared__ char smem[];
    uint32_t sbase = smem_u32(smem);
    int tid = threadIdx.x, wid = tid >> 5, lane = tid & 31;
    int nt = blockIdx.x % n_tiles, mt = blockIdx.x / n_tiles;
    int m0 = mt * 128, n0 = nt * 128;

    int warp_m = (wid >> 2) * 64;         // 0 or 64
    int warp_n = (wid & 3) * 32;          // 0,32,64,96

    // per-thread ldmatrix base offsets (bytes, before kk/array/stage offsets)
    uint32_t aoff = (uint32_t)((warp_m + (lane & 15)) * ROWB + (lane >> 4) * 16);
    uint32_t boff = (uint32_t)((warp_n + ((lane >> 4) << 3) + (lane & 7)) * ROWB
                               + (((lane >> 3) & 1) << 4));

    float acc[4][4][4];
    #pragma unroll
    for (int i = 0; i < 4; ++i)
        #pragma unroll
        for (int j = 0; j < 4; ++j)
            #pragma unroll
            for (int e = 0; e < 4; ++e) acc[i][j][e] = 0.f;

    // ---- chunk loader (cp.async) ----
    auto load_chunk = [&](int c) {
        uint32_t sb = sbase + (uint32_t)(c & 1) * STAGEB;
        const __nv_bfloat16* bases[4] = {
            Ahi + (size_t)m0 * lda + c * 64,
            Alo + (size_t)m0 * lda + c * 64,
            Bhi + (size_t)n0 * ldb + c * 64,
            Blo + (size_t)n0 * ldb + c * 64 };
        #pragma unroll
        for (int arr = 0; arr < 4; ++arr) {
            int ld = (arr < 2) ? lda : ldb;
            #pragma unroll
            for (int q = 0; q < 4; ++q) {
                int t = tid + (arr * 4 + q) * 256;
                int r = (t >> 3) & 127, j = t & 7;
                uint32_t dst = sb + (uint32_t)arr * ARRB + (uint32_t)(r * ROWB + j * 16);
                const void* src = bases[arr] + (size_t)r * ld + j * 8;
                CP16(dst, src);
            }
        }
    };

    load_chunk(0);
    CP_COMMIT();

    for (int c = 0; c < k_chunks; ++c) {
        if (c + 1 < k_chunks) { load_chunk(c + 1); CP_COMMIT(); CP_WAIT1(); }
        else                  { CP_WAIT0(); }
        __syncthreads();

        uint32_t sb = sbase + (uint32_t)(c & 1) * STAGEB;
        uint32_t sAh = sb + aoff;
        uint32_t sAl = sb + ARRB     + aoff;
        uint32_t sBh = sb + 2 * ARRB + boff;
        uint32_t sBl = sb + 3 * ARRB + boff;

        #pragma unroll
        for (int ks = 0; ks < 4; ++ks) {
            uint32_t kb = (uint32_t)(ks * 32);   // 16 bf16 = 32 bytes
            uint32_t bh[8], bl[8];
            LDMX4(bh[0], bh[1], bh[2], bh[3], sBh + kb);
            LDMX4(bh[4], bh[5], bh[6], bh[7], sBh + kb + 16 * ROWB);
            LDMX4(bl[0], bl[1], bl[2], bl[3], sBl + kb);
            LDMX4(bl[4], bl[5], bl[6], bl[7], sBl + kb + 16 * ROWB);
            #pragma unroll
            for (int mi = 0; mi < 4; ++mi) {
                uint32_t ah[4], al[4];
                LDMX4(ah[0], ah[1], ah[2], ah[3], sAh + kb + (uint32_t)(mi * 16 * ROWB));
                LDMX4(al[0], al[1], al[2], al[3], sAl + kb + (uint32_t)(mi * 16 * ROWB));
                #pragma unroll
                for (int ni = 0; ni < 4; ++ni) {
                    MMA16816(acc[mi][ni], ah, bh[2 * ni], bh[2 * ni + 1]);
                    MMA16816(acc[mi][ni], ah, bl[2 * ni], bl[2 * ni + 1]);
                    MMA16816(acc[mi][ni], al, bh[2 * ni], bh[2 * ni + 1]);
                }
            }
        }
        __syncthreads();
    }

    // ---- epilogue ----
    #pragma unroll
    for (int mi = 0; mi < 4; ++mi) {
        int m = m0 + warp_m + mi * 16 + (lane >> 2);
        #pragma unroll
        for (int ni = 0; ni < 4; ++ni) {
            int n = n0 + warp_n + ni * 8 + (lane & 3) * 2;
            float b0 = bias[n], b1 = bias[n + 1];
            float2* p0 = (float2*)(C + (size_t)m * ldc + n);
            float2* p1 = (float2*)(C + (size_t)(m + 8) * ldc + n);
            *p0 = make_float2(acc[mi][ni][0] + b0, acc[mi][ni][1] + b1);
            *p1 = make_float2(acc[mi][ni][2] + b0, acc[mi][ni][3] + b1);
        }
    }
}

// ============================================================================
// attention: CTA per (window b, head h); N=49 tokens, d=64; writes hi/lo bf16
// ============================================================================
__global__ void __launch_bounds__(128) attn_kernel(const float* __restrict__ mask)
{
    __shared__ float qs[49 * 68];
    __shared__ float ks[64 * 68];
    __shared__ float vs[49 * 68];
    __shared__ float ps[4][52];

    int b = blockIdx.x, h = blockIdx.y;
    int tid = threadIdx.x, wid = tid >> 5, lane = tid & 31;
    const float* base = g_qkv + (size_t)b * 49 * 1536 + h * 64;

    // zero garbage K rows 49..63 (read by lane+32 path, masked later)
    for (int t = tid; t < 15 * 68; t += 128) ks[49 * 68 + t] = 0.f;
    // load q/k/v tiles: 3 * 49 * 16 float4
    for (int t = tid; t < 3 * 784; t += 128) {
        int ten = t / 784;
        int rem = t - ten * 784;
        int row = rem >> 4, c4 = rem & 15;
        float4 v4 = *(const float4*)(base + ten * 512 + (size_t)row * 1536 + c4 * 4);
        float* d = (ten == 0 ? qs : ten == 1 ? ks : vs) + row * 68 + c4 * 4;
        *(float4*)d = v4;
    }
    __syncthreads();

    const float* mbase = mask + (size_t)(b & 255) * 2401;
    bool has1 = (lane + 32) < 49;

    for (int r = wid; r < 49; r += 4) {
        const float* qr  = qs + r * 68;
        const float* kr0 = ks + lane * 68;
        const float* kr1 = ks + (lane + 32) * 68;
        float a0 = 0.f, a1 = 0.f;
        #pragma unroll
        for (int d = 0; d < 64; d += 4) {
            float4 q4 = *(const float4*)(qr + d);
            float4 k0 = *(const float4*)(kr0 + d);
            float4 k1 = *(const float4*)(kr1 + d);
            a0 += q4.x * k0.x + q4.y * k0.y + q4.z * k0.z + q4.w * k0.w;
            a1 += q4.x * k1.x + q4.y * k1.y + q4.z * k1.z + q4.w * k1.w;
        }
        float m0v = a0 * 0.125f + mbase[r * 49 + lane];
        float m1v = has1 ? (a1 * 0.125f + mbase[r * 49 + lane + 32]) : -1e30f;
        float mx = fmaxf(m0v, m1v);
        #pragma unroll
        for (int o = 16; o; o >>= 1) mx = fmaxf(mx, __shfl_xor_sync(0xFFFFFFFFu, mx, o));
        float e0 = __expf(m0v - mx);
        float e1 = has1 ? __expf(m1v - mx) : 0.f;
        float s = e0 + e1;
        #pragma unroll
        for (int o = 16; o; o >>= 1) s += __shfl_xor_sync(0xFFFFFFFFu, s, o);
        float inv = __fdividef(1.f, s);
        ps[wid][lane] = e0 * inv;
        if (has1) ps[wid][lane + 32] = e1 * inv;
        __syncwarp();
        float o0 = 0.f, o1 = 0.f;
        #pragma unroll
        for (int m = 0; m < 49; ++m) {
            float p = ps[wid][m];
            o0 += p * vs[m * 68 + lane];
            o1 += p * vs[m * 68 + lane + 32];
        }
        size_t orow = ((size_t)b * 49 + r) * 512 + h * 64;
        __nv_bfloat16 h0, l0, h1, l1;
        split_bf16(o0, h0, l0);
        split_bf16(o1, h1, l1);
        g_att_hi[orow + lane]      = h0;
        g_att_lo[orow + lane]      = l0;
        g_att_hi[orow + lane + 32] = h1;
        g_att_lo[orow + lane + 32] = l1;
        __syncwarp();
    }
}

// ============================================================================
// launch
// ============================================================================
extern "C" void kernel_launch(void* const* d_in, const int* in_sizes, int n_in,
                              void* d_out, int out_size)
{
    const float* x    = (const float*)d_in[0];
    const float* mask = (const float*)d_in[1];
    const float* Wq   = (const float*)d_in[2];
    const float* bq   = (const float*)d_in[3];
    const float* Wk   = (const float*)d_in[4];
    const float* bk   = (const float*)d_in[5];
    const float* Wv   = (const float*)d_in[6];
    const float* bv   = (const float*)d_in[7];
    const float* Wp   = (const float*)d_in[8];
    const float* bp   = (const float*)d_in[9];
    float* out = (float*)d_out;

    cudaFuncSetAttribute(gemm_kernel,
                         cudaFuncAttributeMaxDynamicSharedMemorySize, GEMM_SMEM);

    __nv_bfloat16 *xhi, *xlo, *wqh, *wql, *wph, *wpl, *ath, *atl;
    float *qkv, *bqkv;
    cudaGetSymbolAddress((void**)&xhi,  g_x_hi);
    cudaGetSymbolAddress((void**)&xlo,  g_x_lo);
    cudaGetSymbolAddress((void**)&wqh,  g_wqkv_hi);
    cudaGetSymbolAddress((void**)&wql,  g_wqkv_lo);
    cudaGetSymbolAddress((void**)&wph,  g_wp_hi);
    cudaGetSymbolAddress((void**)&wpl,  g_wp_lo);
    cudaGetSymbolAddress((void**)&ath,  g_att_hi);
    cudaGetSymbolAddress((void**)&atl,  g_att_lo);
    cudaGetSymbolAddress((void**)&qkv,  g_qkv);
    cudaGetSymbolAddress((void**)&bqkv, g_bqkv);

    prep_w_kernel<<<1024, 256>>>(Wq, Wk, Wv, bq, bk, bv, Wp);
    prep_x_kernel<<<8192, 256>>>(x);

    // GEMM1: qkv = x @ Wqkv^T + b   (M=100352, K=1024, N=1536)
    gemm_kernel<<<784 * 12, 256, GEMM_SMEM>>>(
        xhi, xlo, K_QKV, wqh, wql, K_QKV, bqkv, qkv, N_QKV, 12, 16);

    // attention (reads g_qkv, writes g_att_hi/lo)
    attn_kernel<<<dim3(2048, 8), 128>>>(mask);

    // GEMM2: out = att @ Wp + bp    (M=100352, K=512, N=1024)
    gemm_kernel<<<784 * 8, 256, GEMM_SMEM>>>(
        ath, atl, K_PROJ, wph, wpl, K_PROJ, bp, out, N_PROJ, 8, 8);
}